// round 8
// baseline (speedup 1.0000x reference)
#include <cuda_runtime.h>

#define EPSF 1e-6f

// Scratch: [B * (S+1)] records of 36 floats (weighted density matrices).
// Sized for the fixed problem shape B=16384, S=10.
__device__ float g_scratch[16384 * 11 * 36];

__device__ __forceinline__ int tri(int i, int j) { return i * (i + 1) / 2 + j; } // j<=i

// Normalized density matrix (lower-tri, 36 values) for one embedding row.
__device__ __forceinline__ void density36(const float4* __restrict__ row, float r[36]) {
    float p[36];
#pragma unroll
    for (int v = 0; v < 9; v++) {
        float4 q = __ldg(row + v);
        p[4 * v + 0] = q.x; p[4 * v + 1] = q.y; p[4 * v + 2] = q.z; p[4 * v + 3] = q.w;
    }
#pragma unroll
    for (int i = 0; i < 8; i++) p[tri(i, i)] = fmaxf(p[tri(i, i)], 1e-4f);
#pragma unroll
    for (int i = 0; i < 8; i++) {
#pragma unroll
        for (int j = 0; j <= i; j++) {
            float s = 0.f;
#pragma unroll
            for (int k = 0; k <= j; k++) s = fmaf(p[tri(i, k)], p[tri(j, k)], s);
            r[tri(i, j)] = s;
        }
    }
    float trs = 0.f;
#pragma unroll
    for (int i = 0; i < 8; i++) trs += r[tri(i, i)];
    // corr = 1e-6 always (rho = LL^T + eps*I is PD), diag gets eps + 1e-6 = 2e-6
    float inv = __fdividef(1.f, trs + 8.f * 2e-6f + EPSF);
#pragma unroll
    for (int i = 0; i < 36; i++) r[i] *= inv;
#pragma unroll
    for (int i = 0; i < 8; i++) r[tri(i, i)] += 2e-6f * inv;
}

// ---------------- Kernel A: per-(element, slot) density -> scratch ----------------
template <int S>
__global__ void __launch_bounds__(256) dens_kernel(
    const int* __restrict__ contexts, const int* __restrict__ targets,
    const float* __restrict__ emb, int B)
{
    int tid = blockIdx.x * 256 + threadIdx.x;
    int total = B * (S + 1);
    if (tid >= total) return;
    int b = tid / (S + 1);
    int s = tid - b * (S + 1);

    int tok; float w;
    if (s < S) { tok = contexts[b * S + s]; w = (tok != 0) ? 1.f : 0.f; }
    else       { tok = targets[b];          w = 1.f; }

    float r[36];
    density36((const float4*)(emb + (size_t)tok * 36u), r);

    float4* dst = (float4*)(g_scratch + (size_t)tid * 36u);
#pragma unroll
    for (int v = 0; v < 9; v++) {
        float4 q;
        q.x = r[4 * v + 0] * w; q.y = r[4 * v + 1] * w;
        q.z = r[4 * v + 2] * w; q.w = r[4 * v + 3] * w;
        dst[v] = q;
    }
}

// ---------------- Kernel B: fidelity per element ----------------
template <int S>
__global__ void __launch_bounds__(32) fid_kernel(
    const int* __restrict__ contexts, float* __restrict__ out, int B)
{
    int b = blockIdx.x * 32 + threadIdx.x;
    if (b >= B) return;

    // count nonzero context tokens
    float cnt = 0.f;
#pragma unroll
    for (int s = 0; s < S; s++) cnt += (contexts[b * S + s] != 0) ? 1.f : 0.f;

    // accumulate weighted context densities + load target density (high MLP)
    const float4* base = (const float4*)(g_scratch + (size_t)b * (S + 1) * 36u);
    float acc[36], sigma[36];
#pragma unroll
    for (int i = 0; i < 36; i++) acc[i] = 0.f;
#pragma unroll
    for (int s = 0; s < S; s++) {
#pragma unroll
        for (int v = 0; v < 9; v++) {
            float4 q = base[s * 9 + v];
            acc[4 * v + 0] += q.x; acc[4 * v + 1] += q.y;
            acc[4 * v + 2] += q.z; acc[4 * v + 3] += q.w;
        }
    }
#pragma unroll
    for (int v = 0; v < 9; v++) {
        float4 q = base[S * 9 + v];
        sigma[4 * v + 0] = q.x; sigma[4 * v + 1] = q.y;
        sigma[4 * v + 2] = q.z; sigma[4 * v + 3] = q.w;
    }

    // ---- Cholesky of rho_bar + eps*I ----
    float C[36];
    {
        float invc = __fdividef(1.f, cnt);
#pragma unroll
        for (int i = 0; i < 36; i++) C[i] = acc[i] * invc;
#pragma unroll
        for (int i = 0; i < 8; i++) C[tri(i, i)] += EPSF;
#pragma unroll
        for (int j = 0; j < 8; j++) {
            float d = C[tri(j, j)];
#pragma unroll
            for (int k = 0; k < j; k++) d = fmaf(-C[tri(j, k)], C[tri(j, k)], d);
            d = sqrtf(fmaxf(d, 1e-12f));
            C[tri(j, j)] = d;
            float invd = __fdividef(1.f, d);
#pragma unroll
            for (int i = j + 1; i < 8; i++) {
                float v = C[tri(i, j)];
#pragma unroll
                for (int k = 0; k < j; k++) v = fmaf(-C[tri(i, k)], C[tri(j, k)], v);
                C[tri(i, j)] = v * invd;
            }
        }
    }

    // ---- A = C^T * sigma * C (symmetric), eig(A) = eig((rho_bar+eps I) sigma) ----
    float A[8][8];
#pragma unroll
    for (int bc = 0; bc < 8; bc++) {
        float tcol[8];
#pragma unroll
        for (int k = 0; k < 8; k++) {
            float s = 0.f;
#pragma unroll
            for (int m = 0; m < 8; m++) {
                if (m < bc) continue;
                float sg = (k >= m) ? sigma[tri(k, m)] : sigma[tri(m, k)];
                s = fmaf(sg, C[tri(m, bc)], s);
            }
            tcol[k] = s;
        }
#pragma unroll
        for (int a = 0; a < 8; a++) {
            if (a > bc) continue;
            float s = 0.f;
#pragma unroll
            for (int k = 0; k < 8; k++) {
                if (k < a) continue;
                s = fmaf(C[tri(k, a)], tcol[k], s);
            }
            A[a][bc] = s;
            A[bc][a] = s;
        }
    }

    // ---- parallel-ordering cyclic Jacobi: 7 rounds x 4 disjoint pairs, 6 sweeps ----
    // Round-robin tournament schedule (p < q), all 28 pairs per sweep.
    const int JP[7][4] = {{0,1,2,3},{0,2,3,4},{0,1,4,5},{0,2,1,6},{0,3,2,1},{0,4,3,1},{0,5,1,2}};
    const int JQ[7][4] = {{7,6,5,4},{1,7,6,5},{2,3,7,6},{3,4,5,7},{4,5,6,7},{5,6,7,2},{6,7,4,3}};

#pragma unroll 1
    for (int sweep = 0; sweep < 6; sweep++) {
#pragma unroll
        for (int r = 0; r < 7; r++) {
            float c4[4], s4[4], t4[4], o4[4];
            // 4 independent rotation-parameter chains (ILP)
#pragma unroll
            for (int i = 0; i < 4; i++) {
                int p = JP[r][i], q = JQ[r][i];
                float app = A[p][p], aqq = A[q][q], apq = A[p][q];
                float theta = __fdividef(aqq - app, 2.f * apq);
                float t = __fdividef(1.f, fabsf(theta) + sqrtf(fmaf(theta, theta, 1.f)));
                t = copysignf(t, theta);
                t = (fabsf(apq) > 1e-30f) ? t : 0.f;   // also kills NaN theta (0/0)
                float c = rsqrtf(fmaf(t, t, 1.f));
                c4[i] = c; s4[i] = t * c; t4[i] = t; o4[i] = apq;
            }
            // diagonal 2x2 blocks
#pragma unroll
            for (int i = 0; i < 4; i++) {
                int p = JP[r][i], q = JQ[r][i];
                A[p][p] = fmaf(-t4[i], o4[i], A[p][p]);
                A[q][q] = fmaf( t4[i], o4[i], A[q][q]);
                A[p][q] = 0.f; A[q][p] = 0.f;
            }
            // cross 2x2 blocks: rows of pair i, cols of pair j (disjoint => exact)
#pragma unroll
            for (int i = 0; i < 4; i++) {
#pragma unroll
                for (int j = i + 1; j < 4; j++) {
                    int pi = JP[r][i], qi = JQ[r][i];
                    int pj = JP[r][j], qj = JQ[r][j];
                    float a00 = A[pi][pj], a01 = A[pi][qj];
                    float a10 = A[qi][pj], a11 = A[qi][qj];
                    // rows (G_i^T): b0 = c_i*a0 - s_i*a1 ; b1 = s_i*a0 + c_i*a1
                    float b00 = fmaf(c4[i], a00, -s4[i] * a10);
                    float b01 = fmaf(c4[i], a01, -s4[i] * a11);
                    float b10 = fmaf(s4[i], a00,  c4[i] * a10);
                    float b11 = fmaf(s4[i], a01,  c4[i] * a11);
                    // cols (G_j): n_x0 = c_j*b_x0 - s_j*b_x1 ; n_x1 = s_j*b_x0 + c_j*b_x1
                    float n00 = fmaf(c4[j], b00, -s4[j] * b01);
                    float n01 = fmaf(s4[j], b00,  c4[j] * b01);
                    float n10 = fmaf(c4[j], b10, -s4[j] * b11);
                    float n11 = fmaf(s4[j], b10,  c4[j] * b11);
                    A[pi][pj] = n00; A[pi][qj] = n01; A[qi][pj] = n10; A[qi][qj] = n11;
                    A[pj][pi] = n00; A[qj][pi] = n01; A[pj][qi] = n10; A[qj][qi] = n11;
                }
            }
        }
    }

    // ---- f = sum sqrt(lambda + eps), clip, -log ----
    float f = 0.f;
#pragma unroll
    for (int i = 0; i < 8; i++) f += sqrtf(fmaxf(A[i][i], 0.f) + EPSF);
    f = fminf(f, 1.f);
    out[b] = -logf(fmaxf(f, 1e-8f));
}

// ---------------- Fallback: monolithic kernel for unexpected shapes ----------------
__global__ void __launch_bounds__(64) qcbow_fallback(
    const int* __restrict__ contexts, const int* __restrict__ targets,
    const float* __restrict__ emb, float* __restrict__ out, int B, int S)
{
    int b = blockIdx.x * blockDim.x + threadIdx.x;
    if (b >= B) return;

    float acc[36];
#pragma unroll
    for (int i = 0; i < 36; i++) acc[i] = 0.f;
    float cnt = 0.f;
#pragma unroll 1
    for (int s = 0; s < S; s++) {
        int tok = contexts[(long long)b * S + s];
        float r[36];
        density36((const float4*)(emb + (size_t)tok * 36u), r);
        float w = (tok != 0) ? 1.f : 0.f;
        cnt += w;
#pragma unroll
        for (int i = 0; i < 36; i++) acc[i] = fmaf(r[i], w, acc[i]);
    }
    int tt = targets[b];
    float sigma[36];
    density36((const float4*)(emb + (size_t)tt * 36u), sigma);

    float C[36];
    {
        float invc = __fdividef(1.f, cnt);
#pragma unroll
        for (int i = 0; i < 36; i++) C[i] = acc[i] * invc;
#pragma unroll
        for (int i = 0; i < 8; i++) C[tri(i, i)] += EPSF;
#pragma unroll
        for (int j = 0; j < 8; j++) {
            float d = C[tri(j, j)];
#pragma unroll
            for (int k = 0; k < j; k++) d = fmaf(-C[tri(j, k)], C[tri(j, k)], d);
            d = sqrtf(fmaxf(d, 1e-12f));
            C[tri(j, j)] = d;
            float invd = __fdividef(1.f, d);
#pragma unroll
            for (int i = j + 1; i < 8; i++) {
                float v = C[tri(i, j)];
#pragma unroll
                for (int k = 0; k < j; k++) v = fmaf(-C[tri(i, k)], C[tri(j, k)], v);
                C[tri(i, j)] = v * invd;
            }
        }
    }

    float A[8][8];
#pragma unroll
    for (int bc = 0; bc < 8; bc++) {
        float tcol[8];
#pragma unroll
        for (int k = 0; k < 8; k++) {
            float s = 0.f;
#pragma unroll
            for (int m = 0; m < 8; m++) {
                if (m < bc) continue;
                float sg = (k >= m) ? sigma[tri(k, m)] : sigma[tri(m, k)];
                s = fmaf(sg, C[tri(m, bc)], s);
            }
            tcol[k] = s;
        }
#pragma unroll
        for (int a = 0; a < 8; a++) {
            if (a > bc) continue;
            float s = 0.f;
#pragma unroll
            for (int k = 0; k < 8; k++) {
                if (k < a) continue;
                s = fmaf(C[tri(k, a)], tcol[k], s);
            }
            A[a][bc] = s; A[bc][a] = s;
        }
    }

#pragma unroll 1
    for (int sweep = 0; sweep < 6; sweep++) {
#pragma unroll
        for (int p = 0; p < 7; p++) {
#pragma unroll
            for (int q = p + 1; q < 8; q++) {
                float apq = A[p][q];
                float app = A[p][p], aqq = A[q][q];
                float theta = __fdividef(aqq - app, 2.f * apq);
                float t = __fdividef(1.f, fabsf(theta) + sqrtf(fmaf(theta, theta, 1.f)));
                t = copysignf(t, theta);
                t = (fabsf(apq) > 1e-30f) ? t : 0.f;
                float c = rsqrtf(fmaf(t, t, 1.f));
                float s = t * c;
                A[p][p] = fmaf(-t, apq, app);
                A[q][q] = fmaf(t, apq, aqq);
                A[p][q] = 0.f; A[q][p] = 0.f;
#pragma unroll
                for (int k = 0; k < 8; k++) {
                    if (k == p || k == q) continue;
                    float akp = A[k][p], akq = A[k][q];
                    float np = fmaf(c, akp, -s * akq);
                    float nq = fmaf(s, akp, c * akq);
                    A[k][p] = np; A[p][k] = np;
                    A[k][q] = nq; A[q][k] = nq;
                }
            }
        }
    }

    float f = 0.f;
#pragma unroll
    for (int i = 0; i < 8; i++) f += sqrtf(fmaxf(A[i][i], 0.f) + EPSF);
    f = fminf(f, 1.f);
    out[b] = -logf(fmaxf(f, 1e-8f));
}

extern "C" void kernel_launch(void* const* d_in, const int* in_sizes, int n_in,
                              void* d_out, int out_size) {
    const int* contexts = (const int*)d_in[0];
    const int* targets  = (const int*)d_in[1];
    const float* emb    = (const float*)d_in[2];
    float* out          = (float*)d_out;

    int B = in_sizes[1];
    int S = in_sizes[0] / B;

    if (B == 16384 && S == 10) {
        int total = B * 11;
        dens_kernel<10><<<(total + 255) / 256, 256>>>(contexts, targets, emb, B);
        fid_kernel<10><<<(B + 31) / 32, 32>>>(contexts, out, B);
    } else {
        int threads = 64;
        qcbow_fallback<<<(B + threads - 1) / threads, threads>>>(contexts, targets, emb, out, B, S);
    }
}

// round 12
// speedup vs baseline: 1.1334x; 1.1334x over previous
#include <cuda_runtime.h>

#define EPSF 1e-6f

__device__ __forceinline__ int tri(int i, int j) { return i * (i + 1) / 2 + j; } // j<=i

// Symmetric 8x8 stored as lower-tri 36; all uses have compile-time indices.
#define AS(i, j) As[((i) >= (j)) ? ((i) * ((i) + 1) / 2 + (j)) : ((j) * ((j) + 1) / 2 + (i))]

// Normalized density matrix (lower-tri, 36 values) for one embedding row.
__device__ __forceinline__ void density36(const float4* __restrict__ row, float r[36]) {
    float p[36];
#pragma unroll
    for (int v = 0; v < 9; v++) {
        float4 q = __ldg(row + v);
        p[4 * v + 0] = q.x; p[4 * v + 1] = q.y; p[4 * v + 2] = q.z; p[4 * v + 3] = q.w;
    }
#pragma unroll
    for (int i = 0; i < 8; i++) p[tri(i, i)] = fmaxf(p[tri(i, i)], 1e-4f);
#pragma unroll
    for (int i = 0; i < 8; i++) {
#pragma unroll
        for (int j = 0; j <= i; j++) {
            float s = 0.f;
#pragma unroll
            for (int k = 0; k <= j; k++) s = fmaf(p[tri(i, k)], p[tri(j, k)], s);
            r[tri(i, j)] = s;
        }
    }
    float trs = 0.f;
#pragma unroll
    for (int i = 0; i < 8; i++) trs += r[tri(i, i)];
    // corr = 1e-6 always (rho = LL^T + eps*I is PD), diag gets eps + 1e-6 = 2e-6
    float inv = __fdividef(1.f, trs + 8.f * 2e-6f + EPSF);
#pragma unroll
    for (int i = 0; i < 36; i++) r[i] *= inv;
#pragma unroll
    for (int i = 0; i < 8; i++) r[tri(i, i)] += 2e-6f * inv;
}

// ---------------- cooperative kernel: 4 lanes per batch element ----------------
template <int S>
__global__ void __launch_bounds__(128) qcbow_quad(
    const int* __restrict__ contexts,   // [B, S]
    const int* __restrict__ targets,    // [B]
    const float* __restrict__ emb,      // [V, 36]
    float* __restrict__ out,            // [B]
    int B)
{
    int tid = blockIdx.x * 128 + threadIdx.x;
    int b   = tid >> 2;
    int sub = tid & 3;
    bool active = (b < B);
    if (!active) b = 0;               // keep all lanes alive for shuffles

    // ---- phase 1: context densities split across the quad ----
    float acc[36];
#pragma unroll
    for (int i = 0; i < 36; i++) acc[i] = 0.f;
    float cnt = 0.f;

#pragma unroll
    for (int s0 = 0; s0 < S; s0 += 4) {
        int s = s0 + sub;
        if (s < S) {
            int tok = contexts[b * S + s];
            float r[36];
            density36((const float4*)(emb + (size_t)tok * 36u), r);
            float w = (tok != 0) ? 1.f : 0.f;
            cnt += w;
#pragma unroll
            for (int i = 0; i < 36; i++) acc[i] = fmaf(r[i], w, acc[i]);
        }
    }
    // butterfly reduce within the quad; all 4 lanes end bitwise identical
#pragma unroll
    for (int i = 0; i < 36; i++) {
        acc[i] += __shfl_xor_sync(0xffffffffu, acc[i], 1);
        acc[i] += __shfl_xor_sync(0xffffffffu, acc[i], 2);
    }
    cnt += __shfl_xor_sync(0xffffffffu, cnt, 1);
    cnt += __shfl_xor_sync(0xffffffffu, cnt, 2);

    // ---- Cholesky of rho_bar + eps*I, in place in acc (lower C) ----
    {
        float invc = __fdividef(1.f, cnt);
#pragma unroll
        for (int i = 0; i < 36; i++) acc[i] *= invc;
#pragma unroll
        for (int i = 0; i < 8; i++) acc[tri(i, i)] += EPSF;
#pragma unroll
        for (int j = 0; j < 8; j++) {
            float d = acc[tri(j, j)];
#pragma unroll
            for (int k = 0; k < j; k++) d = fmaf(-acc[tri(j, k)], acc[tri(j, k)], d);
            d = sqrtf(fmaxf(d, 1e-12f));
            acc[tri(j, j)] = d;
            float invd = __fdividef(1.f, d);
#pragma unroll
            for (int i = j + 1; i < 8; i++) {
                float v = acc[tri(i, j)];
#pragma unroll
                for (int k = 0; k < j; k++) v = fmaf(-acc[tri(i, k)], acc[tri(j, k)], v);
                acc[tri(i, j)] = v * invd;
            }
        }
    }

    // ---- target density (replicated; same address -> broadcast loads) ----
    float sigma[36];
    density36((const float4*)(emb + (size_t)targets[b] * 36u), sigma);

    // ---- As = C^T * sigma * C (symmetric, lower-tri storage);
    //      eig(As) = eig((rho_bar+eps I) sigma) ----
    float As[36];
#pragma unroll
    for (int bc = 0; bc < 8; bc++) {
        float tcol[8];
#pragma unroll
        for (int k = 0; k < 8; k++) {
            float s = 0.f;
#pragma unroll
            for (int m = 0; m < 8; m++) {
                if (m < bc) continue;                 // C[m][bc]==0 for m<bc
                float sg = (k >= m) ? sigma[tri(k, m)] : sigma[tri(m, k)];
                s = fmaf(sg, acc[tri(m, bc)], s);
            }
            tcol[k] = s;
        }
#pragma unroll
        for (int a = 0; a <= bc; a++) {
            float s = 0.f;
#pragma unroll
            for (int k = 0; k < 8; k++) {
                if (k < a) continue;                  // C[k][a]==0 for k<a
                s = fmaf(acc[tri(k, a)], tcol[k], s);
            }
            As[tri(bc, a)] = s;
        }
    }

    // ---- quad-parallel cyclic Jacobi: each lane owns one pair per round ----
    // Round-robin tournament: 7 rounds x 4 disjoint pairs cover all 28 pairs (p<q).
    const int JP[7][4] = {{0,1,2,3},{0,2,3,4},{0,1,4,5},{0,2,1,6},{0,3,2,1},{0,4,3,1},{0,5,1,2}};
    const int JQ[7][4] = {{7,6,5,4},{1,7,6,5},{2,3,7,6},{3,4,5,7},{4,5,6,7},{5,6,7,2},{6,7,4,3}};

    bool is1 = (sub == 1), is2 = (sub == 2), is3 = (sub == 3);

#pragma unroll 1
    for (int sweep = 0; sweep < 5; sweep++) {
#pragma unroll
        for (int r = 0; r < 7; r++) {
            // select this lane's (app, aqq, apq) -- compile-time indices + SEL tree
            float app, aqq, apq;
            {
                float x0 = As[tri(JP[r][0], JP[r][0])], x1 = As[tri(JP[r][1], JP[r][1])];
                float x2 = As[tri(JP[r][2], JP[r][2])], x3 = As[tri(JP[r][3], JP[r][3])];
                app = is3 ? x3 : (is2 ? x2 : (is1 ? x1 : x0));
                float y0 = As[tri(JQ[r][0], JQ[r][0])], y1 = As[tri(JQ[r][1], JQ[r][1])];
                float y2 = As[tri(JQ[r][2], JQ[r][2])], y3 = As[tri(JQ[r][3], JQ[r][3])];
                aqq = is3 ? y3 : (is2 ? y2 : (is1 ? y1 : y0));
                float z0 = As[tri(JQ[r][0], JP[r][0])], z1 = As[tri(JQ[r][1], JP[r][1])];
                float z2 = As[tri(JQ[r][2], JP[r][2])], z3 = As[tri(JQ[r][3], JP[r][3])];
                apq = is3 ? z3 : (is2 ? z2 : (is1 ? z1 : z0));
            }
            // one rotation-parameter chain per lane
            float theta = __fdividef(aqq - app, 2.f * apq);
            float t = __fdividef(1.f, fabsf(theta) + sqrtf(fmaf(theta, theta, 1.f)));
            t = copysignf(t, theta);
            t = (fabsf(apq) > 1e-30f) ? t : 0.f;   // also kills NaN theta (0/0)
            float c = rsqrtf(fmaf(t, t, 1.f));
            float s = t * c;
            float d = t * apq;

            // exchange (c, s, d) across the quad
            float cj[4], sj[4], dj[4];
#pragma unroll
            for (int j = 0; j < 4; j++) {
                cj[j] = __shfl_sync(0xffffffffu, c, j, 4);
                sj[j] = __shfl_sync(0xffffffffu, s, j, 4);
                dj[j] = __shfl_sync(0xffffffffu, d, j, 4);
            }

            // every lane applies all 4 disjoint rotations to its copy of As
#pragma unroll
            for (int i = 0; i < 4; i++) {
                int p = JP[r][i], q = JQ[r][i];
                As[tri(p, p)] -= dj[i];
                As[tri(q, q)] += dj[i];
                As[tri(q, p)] = 0.f;                  // p<q
            }
#pragma unroll
            for (int i = 0; i < 4; i++) {
#pragma unroll
                for (int j = i + 1; j < 4; j++) {
                    int pi = JP[r][i], qi = JQ[r][i];
                    int pj = JP[r][j], qj = JQ[r][j];
                    float a00 = AS(pi, pj), a01 = AS(pi, qj);
                    float a10 = AS(qi, pj), a11 = AS(qi, qj);
                    // rows (G_i^T)
                    float b00 = fmaf(cj[i], a00, -sj[i] * a10);
                    float b01 = fmaf(cj[i], a01, -sj[i] * a11);
                    float b10 = fmaf(sj[i], a00,  cj[i] * a10);
                    float b11 = fmaf(sj[i], a01,  cj[i] * a11);
                    // cols (G_j)
                    float n00 = fmaf(cj[j], b00, -sj[j] * b01);
                    float n01 = fmaf(sj[j], b00,  cj[j] * b01);
                    float n10 = fmaf(cj[j], b10, -sj[j] * b11);
                    float n11 = fmaf(sj[j], b10,  cj[j] * b11);
                    AS(pi, pj) = n00; AS(pi, qj) = n01;
                    AS(qi, pj) = n10; AS(qi, qj) = n11;
                }
            }
        }
    }

    // ---- f = sum sqrt(lambda + eps), clip, -log ----
    if (active && sub == 0) {
        float f = 0.f;
#pragma unroll
        for (int i = 0; i < 8; i++) f += sqrtf(fmaxf(As[tri(i, i)], 0.f) + EPSF);
        f = fminf(f, 1.f);
        out[b] = -logf(fmaxf(f, 1e-8f));
    }
}

// ---------------- Fallback: monolithic kernel for unexpected shapes ----------------
__global__ void __launch_bounds__(64) qcbow_fallback(
    const int* __restrict__ contexts, const int* __restrict__ targets,
    const float* __restrict__ emb, float* __restrict__ out, int B, int S)
{
    int b = blockIdx.x * blockDim.x + threadIdx.x;
    if (b >= B) return;

    float acc[36];
#pragma unroll
    for (int i = 0; i < 36; i++) acc[i] = 0.f;
    float cnt = 0.f;
#pragma unroll 1
    for (int s = 0; s < S; s++) {
        int tok = contexts[(long long)b * S + s];
        float r[36];
        density36((const float4*)(emb + (size_t)tok * 36u), r);
        float w = (tok != 0) ? 1.f : 0.f;
        cnt += w;
#pragma unroll
        for (int i = 0; i < 36; i++) acc[i] = fmaf(r[i], w, acc[i]);
    }
    int tt = targets[b];
    float sigma[36];
    density36((const float4*)(emb + (size_t)tt * 36u), sigma);

    float C[36];
    {
        float invc = __fdividef(1.f, cnt);
#pragma unroll
        for (int i = 0; i < 36; i++) C[i] = acc[i] * invc;
#pragma unroll
        for (int i = 0; i < 8; i++) C[tri(i, i)] += EPSF;
#pragma unroll
        for (int j = 0; j < 8; j++) {
            float d = C[tri(j, j)];
#pragma unroll
            for (int k = 0; k < j; k++) d = fmaf(-C[tri(j, k)], C[tri(j, k)], d);
            d = sqrtf(fmaxf(d, 1e-12f));
            C[tri(j, j)] = d;
            float invd = __fdividef(1.f, d);
#pragma unroll
            for (int i = j + 1; i < 8; i++) {
                float v = C[tri(i, j)];
#pragma unroll
                for (int k = 0; k < j; k++) v = fmaf(-C[tri(i, k)], C[tri(j, k)], v);
                C[tri(i, j)] = v * invd;
            }
        }
    }

    float A[8][8];
#pragma unroll
    for (int bc = 0; bc < 8; bc++) {
        float tcol[8];
#pragma unroll
        for (int k = 0; k < 8; k++) {
            float s = 0.f;
#pragma unroll
            for (int m = 0; m < 8; m++) {
                if (m < bc) continue;
                float sg = (k >= m) ? sigma[tri(k, m)] : sigma[tri(m, k)];
                s = fmaf(sg, C[tri(m, bc)], s);
            }
            tcol[k] = s;
        }
#pragma unroll
        for (int a = 0; a < 8; a++) {
            if (a > bc) continue;
            float s = 0.f;
#pragma unroll
            for (int k = 0; k < 8; k++) {
                if (k < a) continue;
                s = fmaf(C[tri(k, a)], tcol[k], s);
            }
            A[a][bc] = s; A[bc][a] = s;
        }
    }

#pragma unroll 1
    for (int sweep = 0; sweep < 6; sweep++) {
#pragma unroll
        for (int p = 0; p < 7; p++) {
#pragma unroll
            for (int q = p + 1; q < 8; q++) {
                float apq = A[p][q];
                float app = A[p][p], aqq = A[q][q];
                float theta = __fdividef(aqq - app, 2.f * apq);
                float t = __fdividef(1.f, fabsf(theta) + sqrtf(fmaf(theta, theta, 1.f)));
                t = copysignf(t, theta);
                t = (fabsf(apq) > 1e-30f) ? t : 0.f;
                float c = rsqrtf(fmaf(t, t, 1.f));
                float s = t * c;
                A[p][p] = fmaf(-t, apq, app);
                A[q][q] = fmaf(t, apq, aqq);
                A[p][q] = 0.f; A[q][p] = 0.f;
#pragma unroll
                for (int k = 0; k < 8; k++) {
                    if (k == p || k == q) continue;
                    float akp = A[k][p], akq = A[k][q];
                    float np = fmaf(c, akp, -s * akq);
                    float nq = fmaf(s, akp, c * akq);
                    A[k][p] = np; A[p][k] = np;
                    A[k][q] = nq; A[q][k] = nq;
                }
            }
        }
    }

    float f = 0.f;
#pragma unroll
    for (int i = 0; i < 8; i++) f += sqrtf(fmaxf(A[i][i], 0.f) + EPSF);
    f = fminf(f, 1.f);
    out[b] = -logf(fmaxf(f, 1e-8f));
}

extern "C" void kernel_launch(void* const* d_in, const int* in_sizes, int n_in,
                              void* d_out, int out_size) {
    const int* contexts = (const int*)d_in[0];
    const int* targets  = (const int*)d_in[1];
    const float* emb    = (const float*)d_in[2];
    float* out          = (float*)d_out;

    int B = in_sizes[1];
    int S = in_sizes[0] / B;

    if (S == 10) {
        int total = B * 4;
        qcbow_quad<10><<<(total + 127) / 128, 128>>>(contexts, targets, emb, out, B);
    } else {
        int threads = 64;
        qcbow_fallback<<<(B + threads - 1) / threads, threads>>>(contexts, targets, emb, out, B, S);
    }
}

// round 13
// speedup vs baseline: 1.8094x; 1.5964x over previous
#include <cuda_runtime.h>

#define EPSF 1e-6f

__device__ __forceinline__ int tri(int i, int j) { return i * (i + 1) / 2 + j; } // j<=i

// Symmetric 8x8 stored as lower-tri 36; all uses have compile-time indices.
#define AS(i, j) As[((i) >= (j)) ? ((i) * ((i) + 1) / 2 + (j)) : ((j) * ((j) + 1) / 2 + (i))]

// Weighted-accumulate the normalized density matrix of one embedding row into dst[36]:
// dst += w * rho_norm(row). Low register pressure: diag Gram first -> scale, then
// stream off-diagonals straight into dst (no r[36] temp).
__device__ __forceinline__ void density_acc(const float4* __restrict__ row, float w,
                                            float* __restrict__ dst) {
    float p[36];
#pragma unroll
    for (int v = 0; v < 9; v++) {
        float4 q = __ldg(row + v);
        p[4 * v + 0] = q.x; p[4 * v + 1] = q.y; p[4 * v + 2] = q.z; p[4 * v + 3] = q.w;
    }
#pragma unroll
    for (int i = 0; i < 8; i++) p[tri(i, i)] = fmaxf(p[tri(i, i)], 1e-4f);

    // diagonal Gram entries + trace
    float diag[8];
    float trs = 0.f;
#pragma unroll
    for (int i = 0; i < 8; i++) {
        float s = 0.f;
#pragma unroll
        for (int k = 0; k <= i; k++) s = fmaf(p[tri(i, k)], p[tri(i, k)], s);
        diag[i] = s;
        trs += s;
    }
    // corr = 1e-6 always (rho = LL^T + eps*I is PD) -> diag shift eps+1e-6 = 2e-6
    float inv = w * __fdividef(1.f, trs + 8.f * 2e-6f + EPSF);

#pragma unroll
    for (int i = 0; i < 8; i++)
        dst[tri(i, i)] = fmaf(inv, diag[i] + 2e-6f, dst[tri(i, i)]);
#pragma unroll
    for (int i = 1; i < 8; i++) {
#pragma unroll
        for (int j = 0; j < i; j++) {
            float s = 0.f;
#pragma unroll
            for (int k = 0; k <= j; k++) s = fmaf(p[tri(i, k)], p[tri(j, k)], s);
            dst[tri(i, j)] = fmaf(inv, s, dst[tri(i, j)]);
        }
    }
}

// ---------------- cooperative kernel: 4 lanes per batch element ----------------
template <int S>
__global__ void __launch_bounds__(128, 4) qcbow_quad(
    const int* __restrict__ contexts,   // [B, S]
    const int* __restrict__ targets,    // [B]
    const float* __restrict__ emb,      // [V, 36]
    float* __restrict__ out,            // [B]
    int B)
{
    int tid = blockIdx.x * 128 + threadIdx.x;
    int b   = tid >> 2;
    int sub = tid & 3;
    bool active = (b < B);
    if (!active) b = 0;               // keep all lanes alive for shuffles

    // ---- phase 1: context densities split across the quad ----
    float acc[36];
#pragma unroll
    for (int i = 0; i < 36; i++) acc[i] = 0.f;
    float cnt = 0.f;

#pragma unroll
    for (int s0 = 0; s0 < S; s0 += 4) {
        int s = s0 + sub;
        if (s < S) {
            int tok = contexts[b * S + s];
            float w = (tok != 0) ? 1.f : 0.f;
            cnt += w;
            density_acc((const float4*)(emb + (size_t)tok * 36u), w, acc);
        }
    }
    // butterfly reduce within the quad; all 4 lanes end bitwise identical
#pragma unroll
    for (int i = 0; i < 36; i++) {
        acc[i] += __shfl_xor_sync(0xffffffffu, acc[i], 1);
        acc[i] += __shfl_xor_sync(0xffffffffu, acc[i], 2);
    }
    cnt += __shfl_xor_sync(0xffffffffu, cnt, 1);
    cnt += __shfl_xor_sync(0xffffffffu, cnt, 2);

    // ---- Cholesky of rho_bar + eps*I, in place in acc (lower C) ----
    {
        float invc = __fdividef(1.f, cnt);
#pragma unroll
        for (int i = 0; i < 36; i++) acc[i] *= invc;
#pragma unroll
        for (int i = 0; i < 8; i++) acc[tri(i, i)] += EPSF;
#pragma unroll
        for (int j = 0; j < 8; j++) {
            float d = acc[tri(j, j)];
#pragma unroll
            for (int k = 0; k < j; k++) d = fmaf(-acc[tri(j, k)], acc[tri(j, k)], d);
            d = sqrtf(fmaxf(d, 1e-12f));
            acc[tri(j, j)] = d;
            float invd = __fdividef(1.f, d);
#pragma unroll
            for (int i = j + 1; i < 8; i++) {
                float v = acc[tri(i, j)];
#pragma unroll
                for (int k = 0; k < j; k++) v = fmaf(-acc[tri(i, k)], acc[tri(j, k)], v);
                acc[tri(i, j)] = v * invd;
            }
        }
    }

    // ---- target density (replicated; same address -> broadcast loads) ----
    float sigma[36];
#pragma unroll
    for (int i = 0; i < 36; i++) sigma[i] = 0.f;
    density_acc((const float4*)(emb + (size_t)targets[b] * 36u), 1.f, sigma);

    // ---- As = C^T * sigma * C (symmetric, lower-tri storage);
    //      eig(As) = eig((rho_bar+eps I) sigma) ----
    float As[36];
#pragma unroll
    for (int bc = 0; bc < 8; bc++) {
        float tcol[8];
#pragma unroll
        for (int k = 0; k < 8; k++) {
            float s = 0.f;
#pragma unroll
            for (int m = 0; m < 8; m++) {
                if (m < bc) continue;                 // C[m][bc]==0 for m<bc
                float sg = (k >= m) ? sigma[tri(k, m)] : sigma[tri(m, k)];
                s = fmaf(sg, acc[tri(m, bc)], s);
            }
            tcol[k] = s;
        }
#pragma unroll
        for (int a = 0; a <= bc; a++) {
            float s = 0.f;
#pragma unroll
            for (int k = 0; k < 8; k++) {
                if (k < a) continue;                  // C[k][a]==0 for k<a
                s = fmaf(acc[tri(k, a)], tcol[k], s);
            }
            As[tri(bc, a)] = s;
        }
    }

    // ---- quad-parallel cyclic Jacobi: each lane owns one pair per round ----
    // Round-robin tournament: 7 rounds x 4 disjoint pairs cover all 28 pairs (p<q).
    const int JP[7][4] = {{0,1,2,3},{0,2,3,4},{0,1,4,5},{0,2,1,6},{0,3,2,1},{0,4,3,1},{0,5,1,2}};
    const int JQ[7][4] = {{7,6,5,4},{1,7,6,5},{2,3,7,6},{3,4,5,7},{4,5,6,7},{5,6,7,2},{6,7,4,3}};

    bool is1 = (sub == 1), is2 = (sub == 2), is3 = (sub == 3);

#pragma unroll 1
    for (int sweep = 0; sweep < 4; sweep++) {
#pragma unroll
        for (int r = 0; r < 7; r++) {
            // select this lane's (app, aqq, apq) -- compile-time indices + SEL tree
            float app, aqq, apq;
            {
                float x0 = As[tri(JP[r][0], JP[r][0])], x1 = As[tri(JP[r][1], JP[r][1])];
                float x2 = As[tri(JP[r][2], JP[r][2])], x3 = As[tri(JP[r][3], JP[r][3])];
                app = is3 ? x3 : (is2 ? x2 : (is1 ? x1 : x0));
                float y0 = As[tri(JQ[r][0], JQ[r][0])], y1 = As[tri(JQ[r][1], JQ[r][1])];
                float y2 = As[tri(JQ[r][2], JQ[r][2])], y3 = As[tri(JQ[r][3], JQ[r][3])];
                aqq = is3 ? y3 : (is2 ? y2 : (is1 ? y1 : y0));
                float z0 = As[tri(JQ[r][0], JP[r][0])], z1 = As[tri(JQ[r][1], JP[r][1])];
                float z2 = As[tri(JQ[r][2], JP[r][2])], z3 = As[tri(JQ[r][3], JP[r][3])];
                apq = is3 ? z3 : (is2 ? z2 : (is1 ? z1 : z0));
            }
            // one rotation-parameter chain per lane
            float theta = __fdividef(aqq - app, 2.f * apq);
            float t = __fdividef(1.f, fabsf(theta) + sqrtf(fmaf(theta, theta, 1.f)));
            t = copysignf(t, theta);
            t = (fabsf(apq) > 1e-30f) ? t : 0.f;   // also kills NaN theta (0/0)
            float c = rsqrtf(fmaf(t, t, 1.f));
            float s = t * c;
            float d = t * apq;

            // exchange (c, s, d) across the quad
            float cj[4], sj[4], dj[4];
#pragma unroll
            for (int j = 0; j < 4; j++) {
                cj[j] = __shfl_sync(0xffffffffu, c, j, 4);
                sj[j] = __shfl_sync(0xffffffffu, s, j, 4);
                dj[j] = __shfl_sync(0xffffffffu, d, j, 4);
            }

            // every lane applies all 4 disjoint rotations to its copy of As
#pragma unroll
            for (int i = 0; i < 4; i++) {
                int p = JP[r][i], q = JQ[r][i];
                As[tri(p, p)] -= dj[i];
                As[tri(q, q)] += dj[i];
                As[tri(q, p)] = 0.f;                  // p<q
            }
#pragma unroll
            for (int i = 0; i < 4; i++) {
#pragma unroll
                for (int j = i + 1; j < 4; j++) {
                    int pi = JP[r][i], qi = JQ[r][i];
                    int pj = JP[r][j], qj = JQ[r][j];
                    float a00 = AS(pi, pj), a01 = AS(pi, qj);
                    float a10 = AS(qi, pj), a11 = AS(qi, qj);
                    // rows (G_i^T)
                    float b00 = fmaf(cj[i], a00, -sj[i] * a10);
                    float b01 = fmaf(cj[i], a01, -sj[i] * a11);
                    float b10 = fmaf(sj[i], a00,  cj[i] * a10);
                    float b11 = fmaf(sj[i], a01,  cj[i] * a11);
                    // cols (G_j)
                    float n00 = fmaf(cj[j], b00, -sj[j] * b01);
                    float n01 = fmaf(sj[j], b00,  cj[j] * b01);
                    float n10 = fmaf(cj[j], b10, -sj[j] * b11);
                    float n11 = fmaf(sj[j], b10,  cj[j] * b11);
                    AS(pi, pj) = n00; AS(pi, qj) = n01;
                    AS(qi, pj) = n10; AS(qi, qj) = n11;
                }
            }
        }
    }

    // ---- f = sum sqrt(lambda + eps), clip, -log ----
    if (active && sub == 0) {
        float f = 0.f;
#pragma unroll
        for (int i = 0; i < 8; i++) f += sqrtf(fmaxf(As[tri(i, i)], 0.f) + EPSF);
        f = fminf(f, 1.f);
        out[b] = -logf(fmaxf(f, 1e-8f));
    }
}

// ---------------- Fallback: monolithic kernel for unexpected shapes ----------------
__global__ void __launch_bounds__(64) qcbow_fallback(
    const int* __restrict__ contexts, const int* __restrict__ targets,
    const float* __restrict__ emb, float* __restrict__ out, int B, int S)
{
    int b = blockIdx.x * blockDim.x + threadIdx.x;
    if (b >= B) return;

    float acc[36];
#pragma unroll
    for (int i = 0; i < 36; i++) acc[i] = 0.f;
    float cnt = 0.f;
#pragma unroll 1
    for (int s = 0; s < S; s++) {
        int tok = contexts[(long long)b * S + s];
        float w = (tok != 0) ? 1.f : 0.f;
        cnt += w;
        density_acc((const float4*)(emb + (size_t)tok * 36u), w, acc);
    }
    float sigma[36];
#pragma unroll
    for (int i = 0; i < 36; i++) sigma[i] = 0.f;
    density_acc((const float4*)(emb + (size_t)targets[b] * 36u), 1.f, sigma);

    float C[36];
    {
        float invc = __fdividef(1.f, cnt);
#pragma unroll
        for (int i = 0; i < 36; i++) C[i] = acc[i] * invc;
#pragma unroll
        for (int i = 0; i < 8; i++) C[tri(i, i)] += EPSF;
#pragma unroll
        for (int j = 0; j < 8; j++) {
            float d = C[tri(j, j)];
#pragma unroll
            for (int k = 0; k < j; k++) d = fmaf(-C[tri(j, k)], C[tri(j, k)], d);
            d = sqrtf(fmaxf(d, 1e-12f));
            C[tri(j, j)] = d;
            float invd = __fdividef(1.f, d);
#pragma unroll
            for (int i = j + 1; i < 8; i++) {
                float v = C[tri(i, j)];
#pragma unroll
                for (int k = 0; k < j; k++) v = fmaf(-C[tri(i, k)], C[tri(j, k)], v);
                C[tri(i, j)] = v * invd;
            }
        }
    }

    float A[8][8];
#pragma unroll
    for (int bc = 0; bc < 8; bc++) {
        float tcol[8];
#pragma unroll
        for (int k = 0; k < 8; k++) {
            float s = 0.f;
#pragma unroll
            for (int m = 0; m < 8; m++) {
                if (m < bc) continue;
                float sg = (k >= m) ? sigma[tri(k, m)] : sigma[tri(m, k)];
                s = fmaf(sg, C[tri(m, bc)], s);
            }
            tcol[k] = s;
        }
#pragma unroll
        for (int a = 0; a < 8; a++) {
            if (a > bc) continue;
            float s = 0.f;
#pragma unroll
            for (int k = 0; k < 8; k++) {
                if (k < a) continue;
                s = fmaf(C[tri(k, a)], tcol[k], s);
            }
            A[a][bc] = s; A[bc][a] = s;
        }
    }

#pragma unroll 1
    for (int sweep = 0; sweep < 6; sweep++) {
#pragma unroll
        for (int p = 0; p < 7; p++) {
#pragma unroll
            for (int q = p + 1; q < 8; q++) {
                float apq = A[p][q];
                float app = A[p][p], aqq = A[q][q];
                float theta = __fdividef(aqq - app, 2.f * apq);
                float t = __fdividef(1.f, fabsf(theta) + sqrtf(fmaf(theta, theta, 1.f)));
                t = copysignf(t, theta);
                t = (fabsf(apq) > 1e-30f) ? t : 0.f;
                float c = rsqrtf(fmaf(t, t, 1.f));
                float s = t * c;
                A[p][p] = fmaf(-t, apq, app);
                A[q][q] = fmaf(t, apq, aqq);
                A[p][q] = 0.f; A[q][p] = 0.f;
#pragma unroll
                for (int k = 0; k < 8; k++) {
                    if (k == p || k == q) continue;
                    float akp = A[k][p], akq = A[k][q];
                    float np = fmaf(c, akp, -s * akq);
                    float nq = fmaf(s, akp, c * akq);
                    A[k][p] = np; A[p][k] = np;
                    A[k][q] = nq; A[q][k] = nq;
                }
            }
        }
    }

    float f = 0.f;
#pragma unroll
    for (int i = 0; i < 8; i++) f += sqrtf(fmaxf(A[i][i], 0.f) + EPSF);
    f = fminf(f, 1.f);
    out[b] = -logf(fmaxf(f, 1e-8f));
}

extern "C" void kernel_launch(void* const* d_in, const int* in_sizes, int n_in,
                              void* d_out, int out_size) {
    const int* contexts = (const int*)d_in[0];
    const int* targets  = (const int*)d_in[1];
    const float* emb    = (const float*)d_in[2];
    float* out          = (float*)d_out;

    int B = in_sizes[1];
    int S = in_sizes[0] / B;

    if (S == 10) {
        int total = B * 4;
        qcbow_quad<10><<<(total + 127) / 128, 128>>>(contexts, targets, emb, out, B);
    } else {
        int threads = 64;
        qcbow_fallback<<<(B + threads - 1) / threads, threads>>>(contexts, targets, emb, out, B, S);
    }
}